// round 10
// baseline (speedup 1.0000x reference)
#include <cuda_runtime.h>

// ---------------------------------------------------------------------------
// MomGRU persistent recurrence, round 10 = R9 + beta folded into the GEMM
// butterfly + pre-GEMM straddling the cluster wait.
// Grid 128 CTAs = 32 batch-blocks x 4 hidden-blocks; cluster(4); 256 threads.
// K-permuted smem (own k = local chunks 0-1). Chunk 0 runs BEFORE the wait
// (own data, local), chunk 1 after the wait in the h-LDG shadow. Beta is
// accumulated per-thread during the GEMM and reduced in the same butterfly;
// every thread computes beta(bo) locally -> no beta warp block, one fewer
// __syncthreads. Exchange: stcg/ldcg in L2 + aligned cluster barrier.
// ---------------------------------------------------------------------------

namespace {
constexpr int BATCH = 128;
constexpr int SEQ   = 1024;
constexpr int HID   = 256;
constexpr int GB    = 32;              // batch blocks
constexpr int GH    = 4;               // hidden blocks (= cluster size)
constexpr int NCTA  = GB * GH;         // 128
constexpr int BB    = BATCH / GB;      // 4 batches per CTA
constexpr int UPC   = HID / GH;        // 64 hidden units per CTA
constexpr int NROWS = 3 * UPC;         // 192 W_hh rows per CTA
constexpr int NTH   = 256;
constexpr int RSW   = HID + 16;        // 272 weight row stride (floats)
constexpr int RSH   = HID + 4;         // 260 h row stride (floats)
constexpr int HBUF  = BB * RSH;        // 1040 floats per h buffer

// smem layout (floats)
constexpr int OFF_W   = 0;                       // NROWS * RSW
constexpr int OFF_H   = OFF_W + NROWS * RSW;     // 2 * HBUF (ping-pong)
constexpr int OFF_WBH = OFF_H + 2 * HBUF;        // HID (k-permuted)
constexpr int OFF_WHD = OFF_WBH + HID;           // HID
constexpr int SMEM_FLOATS = OFF_WHD + HID;
constexpr int SMEM_BYTES  = SMEM_FLOATS * 4;     // ~219.3 KB
}

// persistent h ping-pong, layout [buf][batch][hid]
__device__ float g_h[2][BATCH][HID];

// ---- packed fp32x2 helpers -------------------------------------------------
__device__ __forceinline__ unsigned long long pk2(float2 v) {
    unsigned long long r;
    asm("mov.b64 %0, {%1,%2};" : "=l"(r) : "f"(v.x), "f"(v.y));
    return r;
}
__device__ __forceinline__ float2 upk2(unsigned long long v) {
    float2 r;
    asm("mov.b64 {%0,%1}, %2;" : "=f"(r.x), "=f"(r.y) : "l"(v));
    return r;
}
__device__ __forceinline__ float2 ffma2(float2 a, float2 b, float2 c) {
    unsigned long long d;
    asm("fma.rn.f32x2 %0, %1, %2, %3;"
        : "=l"(d) : "l"(pk2(a)), "l"(pk2(b)), "l"(pk2(c)));
    return upk2(d);
}

__device__ __forceinline__ float sigf(float x) {
    return __fdividef(1.0f, 1.0f + __expf(-x));
}
__device__ __forceinline__ float tanh_fast(float x) {
    float ax = fabsf(x);
    float e  = __expf(-2.0f * ax);
    return copysignf(__fdividef(1.0f - e, 1.0f + e), x);
}

// Reduce-scatter over 8 ks lanes (R7-proven).
__device__ __forceinline__ float reduce_scatter8(const float v[8], int ks) {
    float w[4];
    #pragma unroll
    for (int i = 0; i < 4; ++i) {
        float mine  = (ks & 4) ? v[i + 4] : v[i];
        float their = (ks & 4) ? v[i]     : v[i + 4];
        w[i] = mine + __shfl_xor_sync(0xffffffffu, their, 4);
    }
    float y[2];
    #pragma unroll
    for (int i = 0; i < 2; ++i) {
        float mine  = (ks & 2) ? w[i + 2] : w[i];
        float their = (ks & 2) ? w[i]     : w[i + 2];
        y[i] = mine + __shfl_xor_sync(0xffffffffu, their, 2);
    }
    float mine  = (ks & 1) ? y[1] : y[0];
    float their = (ks & 1) ? y[0] : y[1];
    return mine + __shfl_xor_sync(0xffffffffu, their, 1);
}

#define CLUSTER_ARRIVE() asm volatile("barrier.cluster.arrive.aligned;" ::: "memory")
#define CLUSTER_WAIT()   asm volatile("barrier.cluster.wait.aligned;"   ::: "memory")

// One GEMM k-chunk at float offset o_ (compile-time at each call site).
#define GEMM_CHUNK(o_)                                                          \
    {                                                                           \
        const int o = (o_);                                                     \
        float4 h4[4];                                                           \
        _Pragma("unroll")                                                       \
        for (int b = 0; b < 4; ++b)                                             \
            h4[b] = *(const float4*)(hcur + b * RSH + ks * 4 + o);              \
        float4 wb4 = *(const float4*)(wbhs + ks * 4 + o);                       \
        _Pragma("unroll")                                                       \
        for (int b = 0; b < 4; ++b) {                                           \
            bacc[b] = ffma2(make_float2(wb4.x, wb4.y),                          \
                            make_float2(h4[b].x, h4[b].y), bacc[b]);            \
            bacc[b] = ffma2(make_float2(wb4.z, wb4.w),                          \
                            make_float2(h4[b].z, h4[b].w), bacc[b]);            \
        }                                                                       \
        _Pragma("unroll")                                                       \
        for (int g = 0; g < 3; ++g)                                             \
            _Pragma("unroll")                                                   \
            for (int q = 0; q < 2; ++q) {                                       \
                float4 w4 = *(const float4*)(wp[g][q] + o);                     \
                float2 wa = make_float2(w4.x, w4.y);                            \
                float2 wbv = make_float2(w4.z, w4.w);                           \
                _Pragma("unroll")                                               \
                for (int b = 0; b < 4; ++b) {                                   \
                    acc[g][q][b] = ffma2(wa, make_float2(h4[b].x, h4[b].y),     \
                                         acc[g][q][b]);                         \
                    acc[g][q][b] = ffma2(wbv, make_float2(h4[b].z, h4[b].w),    \
                                         acc[g][q][b]);                         \
                }                                                               \
            }                                                                   \
    }

extern "C" __global__ void __launch_bounds__(NTH, 1) __cluster_dims__(GH, 1, 1)
momgru_kernel(const float* __restrict__ x,
              const float* __restrict__ W_ih,
              const float* __restrict__ W_hh,
              const float* __restrict__ b_ih,
              const float* __restrict__ b_hh,
              const float* __restrict__ Wb_x,
              const float* __restrict__ Wb_h,
              const float* __restrict__ b_beta,
              const float* __restrict__ s_ptr,
              const float* __restrict__ W_head,
              const float* __restrict__ b_head,
              float* __restrict__ out)
{
    extern __shared__ float sm[];
    float* ws   = sm + OFF_W;
    float* hbuf = sm + OFF_H;          // [2][BB][RSH], k-permuted
    float* wbhs = sm + OFF_WBH;        // k-permuted
    float* whds = sm + OFF_WHD;        // natural order

    const int tid = threadIdx.x;
    const int j   = blockIdx.x & (GH - 1);    // hidden block / cluster rank
    const int i   = blockIdx.x >> 2;          // batch block
    const int b0  = i * BB;
    const int u0  = j * UPC;

    const int up = tid >> 3;        // 0..31  u-pair index
    const int ks = tid & 7;         // 0..7   K-split lane
    const int uo = up * 2 + (ks >> 2);   // owned local u (0..63)
    const int bo = ks & 3;               // owned local batch (0..3)

    // ---- one-time preload (k-permuted: kl = (k - u0) mod 256) ---------------
    for (int e = tid; e < NROWS * HID; e += NTH) {
        int row = e >> 8;
        int k   = e & (HID - 1);
        int g   = row >> 6;
        int uu  = row & 63;
        int kl  = (k - u0) & (HID - 1);
        ws[row * RSW + kl] = W_hh[(g * HID + u0 + uu) * HID + k];
    }
    for (int e = tid; e < HID; e += NTH) {
        wbhs[(e - u0) & (HID - 1)] = Wb_h[e];
        whds[e] = W_head[e];
    }
    for (int e = tid; e < 2 * HBUF; e += NTH) hbuf[e] = 0.0f;

    const float wbx0  = __ldg(Wb_x);
    const float wbx1  = __ldg(Wb_x + 1);
    const float bbeta = __ldg(b_beta);
    const float sv    = __ldg(s_ptr);
    const float bhead = __ldg(b_head);

    float2 wihg[3];
    float  bihg[3], bhhg[3];
    #pragma unroll
    for (int g = 0; g < 3; ++g) {
        int gr  = g * HID + u0 + uo;
        wihg[g] = make_float2(__ldg(W_ih + gr * 2), __ldg(W_ih + gr * 2 + 1));
        bihg[g] = __ldg(b_ih + gr);
        bhhg[g] = __ldg(b_hh + gr);
    }

    // zero h0 (each CTA zeroes a disjoint 256-float slice of buffer 0)
    {
        float* gz = &g_h[0][0][0];
        __stcg(gz + blockIdx.x * NTH + tid, 0.0f);
    }
    __syncthreads();    // smem zeros visible CTA-wide
    CLUSTER_ARRIVE();   // release: h0 zeros visible at first wait

    // per-thread momentum state for (uo, bo)
    float v0 = 0.f, v1 = 0.f, v2 = 0.f;

    // weight row pointers (k-permuted base + ks lane offset)
    const float* wp[3][2];
    #pragma unroll
    for (int g = 0; g < 3; ++g)
        #pragma unroll
        for (int q = 0; q < 2; ++q)
            wp[g][q] = ws + (g * UPC + up * 2 + q) * RSW + ks * 4;

    // staging permutation for this thread's LDG slot
    const int sb  = tid >> 6;                             // batch row
    const int skl = (((tid & 63) * 4) - u0) & (HID - 1);  // permuted k position

    for (int t = 0; t < SEQ; ++t) {
        float* hcur = hbuf + (t & 1) * HBUF;
        float* hnxt = hbuf + ((t + 1) & 1) * HBUF;

        // per-thread x(bo) prefetch (4 broadcast addresses per CTA)
        float2 xv2 = __ldg((const float2*)x + (b0 + bo) * SEQ + t);

        float2 acc[3][2][4];
        #pragma unroll
        for (int g = 0; g < 3; ++g)
            #pragma unroll
            for (int q = 0; q < 2; ++q)
                #pragma unroll
                for (int b = 0; b < 4; ++b) acc[g][q][b] = make_float2(0.f, 0.f);
        float2 bacc[4];
        #pragma unroll
        for (int b = 0; b < 4; ++b) bacc[b] = make_float2(0.f, 0.f);

        // ---- chunk 0 (own k, local): BEFORE the wait — hides wait/skew ------
        GEMM_CHUNK(0);

        CLUSTER_WAIT();   // acquire: peers' h_t stores visible in L2

        // ---- issue LDG for the full h_t row block ---------------------------
        const float* hsrc = &g_h[t & 1][b0][0];
        float4 hv = __ldcg((const float4*)hsrc + tid);

        // ---- chunk 1 (own k, local): in the LDG shadow ----------------------
        GEMM_CHUNK(32);

        // ---- stage LDG result into hcur at permuted position ----------------
        *(float4*)(hcur + sb * RSH + skl) = hv;
        __syncthreads();

        // ---- main GEMM: local chunks 2..7 -----------------------------------
        #pragma unroll
        for (int kk = 2; kk < 8; ++kk) {
            GEMM_CHUNK(kk * 32);
        }

        // ---- butterfly reduces: 3 gates + beta ------------------------------
        float gh[3];
        #pragma unroll
        for (int g = 0; g < 3; ++g) {
            float v[8];
            #pragma unroll
            for (int q = 0; q < 2; ++q)
                #pragma unroll
                for (int b = 0; b < 4; ++b)
                    v[q * 4 + b] = acc[g][q][b].x + acc[g][q][b].y;
            gh[g] = reduce_scatter8(v, ks) + bhhg[g];
        }
        float bsum;
        {
            float v[8];
            #pragma unroll
            for (int b = 0; b < 4; ++b) { v[b] = bacc[b].x + bacc[b].y; v[b + 4] = 0.f; }
            float sc = reduce_scatter8(v, ks);
            bsum = sc + __shfl_xor_sync(0xffffffffu, sc, 4);
        }

        // ---- v update + gates: thread owns (uo, bo); beta local -------------
        {
            const float bval = sigf(xv2.x * wbx0 + xv2.y * wbx1 + bsum + bbeta);
            if (j == 0 && tid < 4)
                out[BATCH + (b0 + tid) * SEQ + t] = bval;   // tid<4 ⇒ bo = tid

            const float hprev = hcur[bo * RSH + uo];   // permuted: own u at kl=uo

            float pr = xv2.x * wihg[0].x + xv2.y * wihg[0].y + bihg[0];
            float pz = xv2.x * wihg[1].x + xv2.y * wihg[1].y + bihg[1];
            float pn = xv2.x * wihg[2].x + xv2.y * wihg[2].y + bihg[2];
            v0 = bval * v0 + sv * pr;
            v1 = bval * v1 + sv * pz;
            v2 = bval * v2 + sv * pn;

            float r  = sigf(v0 + gh[0]);
            float z  = sigf(v1 + gh[1]);
            float n  = tanh_fast(v2 + r * gh[2]);
            float hn = (1.0f - z) * n + z * hprev;

            hnxt[bo * RSH + uo] = hn;                   // next step's chunk 0/1
            __stcg(&g_h[(t + 1) & 1][b0 + bo][u0 + uo], hn);
        }

        CLUSTER_ARRIVE();  // release h_{t+1} stores
        __syncthreads();   // hnxt own-region visible before next pre-GEMM
    }

    CLUSTER_WAIT();        // final h_T (buffer 0) visible

    // ---- head: out[b] = h_T . W_head + b_head (rank-0 CTA per batch block) ---
    if (j == 0 && tid < 64) {
        int b  = tid >> 4;
        int kc = tid & 15;
        const float* hT = &g_h[0][b0 + b][0];
        float2 a2 = make_float2(0.f, 0.f);
        #pragma unroll
        for (int kk = 0; kk < 4; ++kk) {
            float4 h4 = __ldcg((const float4*)(hT + kc * 4 + kk * 64));
            float4 w4 = *(const float4*)(whds + kc * 4 + kk * 64);
            a2 = ffma2(make_float2(w4.x, w4.y), make_float2(h4.x, h4.y), a2);
            a2 = ffma2(make_float2(w4.z, w4.w), make_float2(h4.z, h4.w), a2);
        }
        float a = a2.x + a2.y;
        a += __shfl_xor_sync(0xffffffffu, a, 1);
        a += __shfl_xor_sync(0xffffffffu, a, 2);
        a += __shfl_xor_sync(0xffffffffu, a, 4);
        a += __shfl_xor_sync(0xffffffffu, a, 8);
        if (kc == 0) out[b0 + b] = a + bhead;
    }
}

extern "C" void kernel_launch(void* const* d_in, const int* in_sizes, int n_in,
                              void* d_out, int out_size) {
    const float* x      = (const float*)d_in[0];
    const float* W_ih   = (const float*)d_in[1];
    const float* W_hh   = (const float*)d_in[2];
    const float* b_ih   = (const float*)d_in[3];
    const float* b_hh   = (const float*)d_in[4];
    const float* Wb_x   = (const float*)d_in[5];
    const float* Wb_h   = (const float*)d_in[6];
    const float* b_beta = (const float*)d_in[7];
    const float* s      = (const float*)d_in[8];
    const float* W_head = (const float*)d_in[9];
    const float* b_head = (const float*)d_in[10];

    cudaFuncSetAttribute(momgru_kernel,
                         cudaFuncAttributeMaxDynamicSharedMemorySize,
                         SMEM_BYTES);

    momgru_kernel<<<NCTA, NTH, SMEM_BYTES>>>(
        x, W_ih, W_hh, b_ih, b_hh, Wb_x, Wb_h, b_beta, s, W_head, b_head,
        (float*)d_out);
}

// round 11
// speedup vs baseline: 1.1817x; 1.1817x over previous
#include <cuda_runtime.h>

// ---------------------------------------------------------------------------
// MomGRU persistent recurrence, round 11 = R9 with the h exchange moved to
// direct DSMEM pushes (ownership-sized) + HW tanh activations.
// Grid 128 CTAs = 32 batch-blocks x 4 hidden-blocks; cluster(4); 256 threads.
// K-permuted smem; ping-pong h buffers IN SMEM are the only h storage:
// each thread owns one (u,b) value and pushes it to the 3 peer CTAs via
// st.shared::cluster (+1 local STS). The aligned cluster barrier provides
// release/acquire for the pushes. No g_h global, no LDG/stage in the loop.
// Own k-chunks 0-1 run before the wait (local data, R9-proven overlap).
// ---------------------------------------------------------------------------

namespace {
constexpr int BATCH = 128;
constexpr int SEQ   = 1024;
constexpr int HID   = 256;
constexpr int GB    = 32;              // batch blocks
constexpr int GH    = 4;               // hidden blocks (= cluster size)
constexpr int NCTA  = GB * GH;         // 128
constexpr int BB    = BATCH / GB;      // 4 batches per CTA
constexpr int UPC   = HID / GH;        // 64 hidden units per CTA
constexpr int NROWS = 3 * UPC;         // 192 W_hh rows per CTA
constexpr int NTH   = 256;
constexpr int RSW   = HID + 16;        // 272 weight row stride (floats)
constexpr int RSH   = HID + 4;         // 260 h row stride (floats)
constexpr int HBUF  = BB * RSH;        // 1040 floats per h buffer

// smem layout (floats)
constexpr int OFF_W   = 0;                       // NROWS * RSW
constexpr int OFF_H   = OFF_W + NROWS * RSW;     // 2 * HBUF (ping-pong)
constexpr int OFF_WBH = OFF_H + 2 * HBUF;        // HID (k-permuted)
constexpr int OFF_WHD = OFF_WBH + HID;           // HID
constexpr int OFF_BS  = OFF_WHD + HID;           // BB
constexpr int OFF_XS  = OFF_BS + BB;             // BB float2
constexpr int SMEM_FLOATS = OFF_XS + BB * 2;
constexpr int SMEM_BYTES  = SMEM_FLOATS * 4;     // ~219.4 KB
}

// ---- packed fp32x2 helpers -------------------------------------------------
__device__ __forceinline__ unsigned long long pk2(float2 v) {
    unsigned long long r;
    asm("mov.b64 %0, {%1,%2};" : "=l"(r) : "f"(v.x), "f"(v.y));
    return r;
}
__device__ __forceinline__ float2 upk2(unsigned long long v) {
    float2 r;
    asm("mov.b64 {%0,%1}, %2;" : "=f"(r.x), "=f"(r.y) : "l"(v));
    return r;
}
__device__ __forceinline__ float2 ffma2(float2 a, float2 b, float2 c) {
    unsigned long long d;
    asm("fma.rn.f32x2 %0, %1, %2, %3;"
        : "=l"(d) : "l"(pk2(a)), "l"(pk2(b)), "l"(pk2(c)));
    return upk2(d);
}

// ---- HW tanh activations ----------------------------------------------------
__device__ __forceinline__ float tanh_hw(float x) {
    float r;
    asm("tanh.approx.f32 %0, %1;" : "=f"(r) : "f"(x));
    return r;
}
__device__ __forceinline__ float sigf(float x) {
    return 0.5f + 0.5f * tanh_hw(0.5f * x);
}

// ---- DSMEM helpers -----------------------------------------------------------
__device__ __forceinline__ unsigned smem_u32(const void* p) {
    unsigned a;
    asm("{ .reg .u64 t; cvta.to.shared.u64 t, %1; cvt.u32.u64 %0, t; }"
        : "=r"(a) : "l"(p));
    return a;
}
__device__ __forceinline__ unsigned mapa_rank(unsigned local, unsigned rank) {
    unsigned r;
    asm("mapa.shared::cluster.u32 %0, %1, %2;" : "=r"(r) : "r"(local), "r"(rank));
    return r;
}
__device__ __forceinline__ void st_cluster_f32(unsigned addr, float v) {
    asm volatile("st.shared::cluster.f32 [%0], %1;" :: "r"(addr), "f"(v) : "memory");
}

// Reduce-scatter over 8 ks lanes (R7-proven).
__device__ __forceinline__ float reduce_scatter8(const float v[8], int ks) {
    float w[4];
    #pragma unroll
    for (int i = 0; i < 4; ++i) {
        float mine  = (ks & 4) ? v[i + 4] : v[i];
        float their = (ks & 4) ? v[i]     : v[i + 4];
        w[i] = mine + __shfl_xor_sync(0xffffffffu, their, 4);
    }
    float y[2];
    #pragma unroll
    for (int i = 0; i < 2; ++i) {
        float mine  = (ks & 2) ? w[i + 2] : w[i];
        float their = (ks & 2) ? w[i]     : w[i + 2];
        y[i] = mine + __shfl_xor_sync(0xffffffffu, their, 2);
    }
    float mine  = (ks & 1) ? y[1] : y[0];
    float their = (ks & 1) ? y[0] : y[1];
    return mine + __shfl_xor_sync(0xffffffffu, their, 1);
}

#define CLUSTER_ARRIVE() asm volatile("barrier.cluster.arrive.aligned;" ::: "memory")
#define CLUSTER_WAIT()   asm volatile("barrier.cluster.wait.aligned;"   ::: "memory")

// One GEMM k-chunk at float offset o_ (compile-time at each call site).
#define GEMM_CHUNK(o_)                                                          \
    {                                                                           \
        const int o = (o_);                                                     \
        float4 h4[4];                                                           \
        _Pragma("unroll")                                                       \
        for (int b = 0; b < 4; ++b)                                             \
            h4[b] = *(const float4*)(hcur + b * RSH + ks * 4 + o);              \
        _Pragma("unroll")                                                       \
        for (int g = 0; g < 3; ++g)                                             \
            _Pragma("unroll")                                                   \
            for (int q = 0; q < 2; ++q) {                                       \
                float4 w4 = *(const float4*)(wp[g][q] + o);                     \
                float2 wa = make_float2(w4.x, w4.y);                            \
                float2 wb = make_float2(w4.z, w4.w);                            \
                _Pragma("unroll")                                               \
                for (int b = 0; b < 4; ++b) {                                   \
                    acc[g][q][b] = ffma2(wa, make_float2(h4[b].x, h4[b].y),     \
                                         acc[g][q][b]);                         \
                    acc[g][q][b] = ffma2(wb, make_float2(h4[b].z, h4[b].w),     \
                                         acc[g][q][b]);                         \
                }                                                               \
            }                                                                   \
    }

extern "C" __global__ void __launch_bounds__(NTH, 1) __cluster_dims__(GH, 1, 1)
momgru_kernel(const float* __restrict__ x,
              const float* __restrict__ W_ih,
              const float* __restrict__ W_hh,
              const float* __restrict__ b_ih,
              const float* __restrict__ b_hh,
              const float* __restrict__ Wb_x,
              const float* __restrict__ Wb_h,
              const float* __restrict__ b_beta,
              const float* __restrict__ s_ptr,
              const float* __restrict__ W_head,
              const float* __restrict__ b_head,
              float* __restrict__ out)
{
    extern __shared__ float sm[];
    float*  ws     = sm + OFF_W;
    float*  hbuf   = sm + OFF_H;        // [2][BB][RSH], k-permuted, DSMEM target
    float*  wbhs   = sm + OFF_WBH;      // k-permuted
    float*  whds   = sm + OFF_WHD;
    float*  beta_s = sm + OFF_BS;
    float2* xs     = (float2*)(sm + OFF_XS);

    const int tid = threadIdx.x;
    const int j   = blockIdx.x & (GH - 1);    // hidden block / cluster rank
    const int i   = blockIdx.x >> 2;          // batch block
    const int b0  = i * BB;
    const int u0  = j * UPC;

    const int up = tid >> 3;        // 0..31  u-pair index
    const int ks = tid & 7;         // 0..7   K-split lane
    const int uo = up * 2 + (ks >> 2);   // owned local u (0..63)
    const int bo = ks & 3;               // owned local batch (0..3)

    // ---- one-time preload (k-permuted: kl = (k - u0) mod 256) ---------------
    for (int e = tid; e < NROWS * HID; e += NTH) {
        int row = e >> 8;
        int k   = e & (HID - 1);
        int g   = row >> 6;
        int uu  = row & 63;
        int kl  = (k - u0) & (HID - 1);
        ws[row * RSW + kl] = W_hh[(g * HID + u0 + uu) * HID + k];
    }
    for (int e = tid; e < HID; e += NTH) {
        wbhs[(e - u0) & (HID - 1)] = Wb_h[e];
        whds[e] = W_head[e];
    }
    // zero both h buffers: h0 = 0 for step-0 reads everywhere
    for (int e = tid; e < 2 * HBUF; e += NTH) hbuf[e] = 0.0f;

    const float wbx0  = __ldg(Wb_x);
    const float wbx1  = __ldg(Wb_x + 1);
    const float bbeta = __ldg(b_beta);
    const float sv    = __ldg(s_ptr);
    const float bhead = __ldg(b_head);

    float2 wihg[3];
    float  bihg[3], bhhg[3];
    #pragma unroll
    for (int g = 0; g < 3; ++g) {
        int gr  = g * HID + u0 + uo;
        wihg[g] = make_float2(__ldg(W_ih + gr * 2), __ldg(W_ih + gr * 2 + 1));
        bihg[g] = __ldg(b_ih + gr);
        bhhg[g] = __ldg(b_hh + gr);
    }

    // DSMEM push addresses: this thread's (uo,bo) into each peer's buffer,
    // at the PEER's k-permuted position kl_p = (u0 + uo - 64p) mod 256.
    const unsigned hbase = smem_u32(hbuf);
    unsigned hpush[GH - 1];
    {
        int idx = 0;
        for (int p = 0; p < GH; ++p) {
            if (p == j) continue;
            int klp = ((u0 + uo) - UPC * p) & (HID - 1);
            hpush[idx++] = mapa_rank(hbase, (unsigned)p)
                         + (unsigned)(bo * RSH + klp) * 4u;
        }
    }

    __syncthreads();    // smem zeros + weights visible CTA-wide
    CLUSTER_ARRIVE();   // release: peers may start reading (zeros) after wait

    // per-thread momentum state for (uo, bo)
    float v0 = 0.f, v1 = 0.f, v2 = 0.f;

    // weight row pointers (k-permuted base + ks lane offset)
    const float* wp[3][2];
    #pragma unroll
    for (int g = 0; g < 3; ++g)
        #pragma unroll
        for (int q = 0; q < 2; ++q)
            wp[g][q] = ws + (g * UPC + up * 2 + q) * RSW + ks * 4;

    const int bb = tid >> 4;        // beta batch (tid<64): 0..3
    const int kc = tid & 15;        // beta K-chunk lane

    for (int t = 0; t < SEQ; ++t) {
        float* hcur = hbuf + (t & 1) * HBUF;
        float* hnxt = hbuf + ((t + 1) & 1) * HBUF;
        const unsigned boff = (unsigned)(((t + 1) & 1) * HBUF) * 4u;

        // x prefetch BEFORE the wait (independent of peers' h)
        float2 xv = make_float2(0.f, 0.f);
        if (tid < 64 && kc == 0)
            xv = __ldg((const float2*)x + (b0 + bb) * SEQ + t);

        float2 acc[3][2][4];
        #pragma unroll
        for (int g = 0; g < 3; ++g)
            #pragma unroll
            for (int q = 0; q < 2; ++q)
                #pragma unroll
                for (int b = 0; b < 4; ++b) acc[g][q][b] = make_float2(0.f, 0.f);

        // ---- chunks 0-1 (own k, local, written by own gates at t-1) ---------
        GEMM_CHUNK(0);
        GEMM_CHUNK(32);

        CLUSTER_WAIT();   // acquire: peers' pushes into hcur visible

        // ---- beta: h . Wb_h (warps 0-1; permuted order, same dot) -----------
        if (tid < 64) {
            const float* hrow = hcur + bb * RSH + kc * 4;
            const float* wrow = wbhs + kc * 4;
            float2 a2 = make_float2(0.f, 0.f);
            #pragma unroll
            for (int kk = 0; kk < 4; ++kk) {
                float4 h4 = *(const float4*)(hrow + kk * 64);
                float4 w4 = *(const float4*)(wrow + kk * 64);
                a2 = ffma2(make_float2(w4.x, w4.y), make_float2(h4.x, h4.y), a2);
                a2 = ffma2(make_float2(w4.z, w4.w), make_float2(h4.z, h4.w), a2);
            }
            float a = a2.x + a2.y;
            a += __shfl_xor_sync(0xffffffffu, a, 1);
            a += __shfl_xor_sync(0xffffffffu, a, 2);
            a += __shfl_xor_sync(0xffffffffu, a, 4);
            a += __shfl_xor_sync(0xffffffffu, a, 8);
            if (kc == 0) {
                float bval = sigf(xv.x * wbx0 + xv.y * wbx1 + a + bbeta);
                beta_s[bb] = bval;
                xs[bb]     = xv;
                if (j == 0) out[BATCH + (b0 + bb) * SEQ + t] = bval;
            }
        }

        // ---- main GEMM: local chunks 2..7 (peer data) -----------------------
        #pragma unroll
        for (int kk = 2; kk < 8; ++kk) {
            GEMM_CHUNK(kk * 32);
        }

        // ---- reduce-scatter over ks lanes: thread keeps its own (uo,bo) -----
        float gh[3];
        #pragma unroll
        for (int g = 0; g < 3; ++g) {
            float v[8];
            #pragma unroll
            for (int q = 0; q < 2; ++q)
                #pragma unroll
                for (int b = 0; b < 4; ++b)
                    v[q * 4 + b] = acc[g][q][b].x + acc[g][q][b].y;
            gh[g] = reduce_scatter8(v, ks) + bhhg[g];
        }

        __syncthreads();   // beta_s / xs published; hcur reads of step t done

        // ---- v update + gates: thread owns (uo, bo) -------------------------
        {
            const float  be    = beta_s[bo];
            const float2 xv2   = xs[bo];
            const float  hprev = hcur[bo * RSH + uo];   // own u at kl=uo

            float pr = xv2.x * wihg[0].x + xv2.y * wihg[0].y + bihg[0];
            float pz = xv2.x * wihg[1].x + xv2.y * wihg[1].y + bihg[1];
            float pn = xv2.x * wihg[2].x + xv2.y * wihg[2].y + bihg[2];
            v0 = be * v0 + sv * pr;
            v1 = be * v1 + sv * pz;
            v2 = be * v2 + sv * pn;

            float r  = sigf(v0 + gh[0]);
            float z  = sigf(v1 + gh[1]);
            float n  = tanh_hw(v2 + r * gh[2]);
            float hn = (1.0f - z) * n + z * hprev;

            // publish h_{t+1}(u0+uo, bo): 3 DSMEM pushes + 1 local store
            st_cluster_f32(hpush[0] + boff, hn);
            st_cluster_f32(hpush[1] + boff, hn);
            st_cluster_f32(hpush[2] + boff, hn);
            hnxt[bo * RSH + uo] = hn;
        }

        CLUSTER_ARRIVE();  // release: pushes ordered before peers' next wait
        __syncthreads();   // own-region hnxt visible before next chunks 0-1
    }

    CLUSTER_WAIT();        // final pushes visible; h_T = buffer 0 in smem

    // ---- head: out[b] = h_T . W_head + b_head (rank-0 CTA; u0=0 -> natural) -
    if (j == 0 && tid < 64) {
        int b = tid >> 4;
        const float* hT = hbuf + b * RSH;          // buffer 0
        float2 a2 = make_float2(0.f, 0.f);
        #pragma unroll
        for (int kk = 0; kk < 4; ++kk) {
            float4 h4 = *(const float4*)(hT + kc * 4 + kk * 64);
            float4 w4 = *(const float4*)(whds + kc * 4 + kk * 64);
            a2 = ffma2(make_float2(w4.x, w4.y), make_float2(h4.x, h4.y), a2);
            a2 = ffma2(make_float2(w4.z, w4.w), make_float2(h4.z, h4.w), a2);
        }
        float a = a2.x + a2.y;
        a += __shfl_xor_sync(0xffffffffu, a, 1);
        a += __shfl_xor_sync(0xffffffffu, a, 2);
        a += __shfl_xor_sync(0xffffffffu, a, 4);
        a += __shfl_xor_sync(0xffffffffu, a, 8);
        if (kc == 0) out[b0 + b] = a + bhead;
    }

    CLUSTER_ARRIVE();      // no CTA exits while peers may still push into it
    CLUSTER_WAIT();
}

extern "C" void kernel_launch(void* const* d_in, const int* in_sizes, int n_in,
                              void* d_out, int out_size) {
    const float* x      = (const float*)d_in[0];
    const float* W_ih   = (const float*)d_in[1];
    const float* W_hh   = (const float*)d_in[2];
    const float* b_ih   = (const float*)d_in[3];
    const float* b_hh   = (const float*)d_in[4];
    const float* Wb_x   = (const float*)d_in[5];
    const float* Wb_h   = (const float*)d_in[6];
    const float* b_beta = (const float*)d_in[7];
    const float* s      = (const float*)d_in[8];
    const float* W_head = (const float*)d_in[9];
    const float* b_head = (const float*)d_in[10];

    cudaFuncSetAttribute(momgru_kernel,
                         cudaFuncAttributeMaxDynamicSharedMemorySize,
                         SMEM_BYTES);

    momgru_kernel<<<NCTA, NTH, SMEM_BYTES>>>(
        x, W_ih, W_hh, b_ih, b_hh, Wb_x, Wb_h, b_beta, s, W_head, b_head,
        (float*)d_out);
}

// round 12
// speedup vs baseline: 1.2539x; 1.0611x over previous
#include <cuda_runtime.h>

// ---------------------------------------------------------------------------
// MomGRU persistent recurrence, round 12 = R11 + register-resident weights
// for the CTA's own k-chunks (0-1).
// Grid 128 CTAs = 32 batch-blocks x 4 hidden-blocks; cluster(4); 256 threads.
// K-permuted smem; h lives ONLY in smem ping-pong buffers; each thread owns
// one (u,b) value and pushes it to the 3 peer CTAs via st.shared::cluster.
// Own chunks 0-1 (pre-wait) now read weights from registers (48 regs), not
// smem: weight crossbar 1536 -> 1152 cyc/step and denser pre-wait issue.
// ---------------------------------------------------------------------------

namespace {
constexpr int BATCH = 128;
constexpr int SEQ   = 1024;
constexpr int HID   = 256;
constexpr int GB    = 32;              // batch blocks
constexpr int GH    = 4;               // hidden blocks (= cluster size)
constexpr int NCTA  = GB * GH;         // 128
constexpr int BB    = BATCH / GB;      // 4 batches per CTA
constexpr int UPC   = HID / GH;        // 64 hidden units per CTA
constexpr int NROWS = 3 * UPC;         // 192 W_hh rows per CTA
constexpr int NTH   = 256;
constexpr int RSW   = HID + 16;        // 272 weight row stride (floats)
constexpr int RSH   = HID + 4;         // 260 h row stride (floats)
constexpr int HBUF  = BB * RSH;        // 1040 floats per h buffer

// smem layout (floats)
constexpr int OFF_W   = 0;                       // NROWS * RSW
constexpr int OFF_H   = OFF_W + NROWS * RSW;     // 2 * HBUF (ping-pong)
constexpr int OFF_WBH = OFF_H + 2 * HBUF;        // HID (k-permuted)
constexpr int OFF_WHD = OFF_WBH + HID;           // HID
constexpr int OFF_BS  = OFF_WHD + HID;           // BB
constexpr int OFF_XS  = OFF_BS + BB;             // BB float2
constexpr int SMEM_FLOATS = OFF_XS + BB * 2;
constexpr int SMEM_BYTES  = SMEM_FLOATS * 4;     // ~219.4 KB
}

// ---- packed fp32x2 helpers -------------------------------------------------
__device__ __forceinline__ unsigned long long pk2(float2 v) {
    unsigned long long r;
    asm("mov.b64 %0, {%1,%2};" : "=l"(r) : "f"(v.x), "f"(v.y));
    return r;
}
__device__ __forceinline__ float2 upk2(unsigned long long v) {
    float2 r;
    asm("mov.b64 {%0,%1}, %2;" : "=f"(r.x), "=f"(r.y) : "l"(v));
    return r;
}
__device__ __forceinline__ float2 ffma2(float2 a, float2 b, float2 c) {
    unsigned long long d;
    asm("fma.rn.f32x2 %0, %1, %2, %3;"
        : "=l"(d) : "l"(pk2(a)), "l"(pk2(b)), "l"(pk2(c)));
    return upk2(d);
}

// ---- HW tanh activations ----------------------------------------------------
__device__ __forceinline__ float tanh_hw(float x) {
    float r;
    asm("tanh.approx.f32 %0, %1;" : "=f"(r) : "f"(x));
    return r;
}
__device__ __forceinline__ float sigf(float x) {
    return 0.5f + 0.5f * tanh_hw(0.5f * x);
}

// ---- DSMEM helpers -----------------------------------------------------------
__device__ __forceinline__ unsigned smem_u32(const void* p) {
    unsigned a;
    asm("{ .reg .u64 t; cvta.to.shared.u64 t, %1; cvt.u32.u64 %0, t; }"
        : "=r"(a) : "l"(p));
    return a;
}
__device__ __forceinline__ unsigned mapa_rank(unsigned local, unsigned rank) {
    unsigned r;
    asm("mapa.shared::cluster.u32 %0, %1, %2;" : "=r"(r) : "r"(local), "r"(rank));
    return r;
}
__device__ __forceinline__ void st_cluster_f32(unsigned addr, float v) {
    asm volatile("st.shared::cluster.f32 [%0], %1;" :: "r"(addr), "f"(v) : "memory");
}

// Reduce-scatter over 8 ks lanes (R7-proven).
__device__ __forceinline__ float reduce_scatter8(const float v[8], int ks) {
    float w[4];
    #pragma unroll
    for (int i = 0; i < 4; ++i) {
        float mine  = (ks & 4) ? v[i + 4] : v[i];
        float their = (ks & 4) ? v[i]     : v[i + 4];
        w[i] = mine + __shfl_xor_sync(0xffffffffu, their, 4);
    }
    float y[2];
    #pragma unroll
    for (int i = 0; i < 2; ++i) {
        float mine  = (ks & 2) ? w[i + 2] : w[i];
        float their = (ks & 2) ? w[i]     : w[i + 2];
        y[i] = mine + __shfl_xor_sync(0xffffffffu, their, 2);
    }
    float mine  = (ks & 1) ? y[1] : y[0];
    float their = (ks & 1) ? y[0] : y[1];
    return mine + __shfl_xor_sync(0xffffffffu, their, 1);
}

#define CLUSTER_ARRIVE() asm volatile("barrier.cluster.arrive.aligned;" ::: "memory")
#define CLUSTER_WAIT()   asm volatile("barrier.cluster.wait.aligned;"   ::: "memory")

// GEMM k-chunk with weights from SMEM (chunks 2..7).
#define GEMM_CHUNK(o_)                                                          \
    {                                                                           \
        const int o = (o_);                                                     \
        float4 h4[4];                                                           \
        _Pragma("unroll")                                                       \
        for (int b = 0; b < 4; ++b)                                             \
            h4[b] = *(const float4*)(hcur + b * RSH + ks * 4 + o);              \
        _Pragma("unroll")                                                       \
        for (int g = 0; g < 3; ++g)                                             \
            _Pragma("unroll")                                                   \
            for (int q = 0; q < 2; ++q) {                                       \
                float4 w4 = *(const float4*)(wp[g][q] + o);                     \
                float2 wa = make_float2(w4.x, w4.y);                            \
                float2 wb = make_float2(w4.z, w4.w);                            \
                _Pragma("unroll")                                               \
                for (int b = 0; b < 4; ++b) {                                   \
                    acc[g][q][b] = ffma2(wa, make_float2(h4[b].x, h4[b].y),     \
                                         acc[g][q][b]);                         \
                    acc[g][q][b] = ffma2(wb, make_float2(h4[b].z, h4[b].w),     \
                                         acc[g][q][b]);                         \
                }                                                               \
            }                                                                   \
    }

// GEMM k-chunk with weights from REGISTERS (own chunks 0..1; kkidx = 0 or 1).
#define GEMM_CHUNK_REG(kkidx)                                                   \
    {                                                                           \
        const int o = (kkidx) * 32;                                             \
        float4 h4[4];                                                           \
        _Pragma("unroll")                                                       \
        for (int b = 0; b < 4; ++b)                                             \
            h4[b] = *(const float4*)(hcur + b * RSH + ks * 4 + o);              \
        _Pragma("unroll")                                                       \
        for (int g = 0; g < 3; ++g)                                             \
            _Pragma("unroll")                                                   \
            for (int q = 0; q < 2; ++q) {                                       \
                float4 w4 = wreg[g][q][kkidx];                                  \
                float2 wa = make_float2(w4.x, w4.y);                            \
                float2 wb = make_float2(w4.z, w4.w);                            \
                _Pragma("unroll")                                               \
                for (int b = 0; b < 4; ++b) {                                   \
                    acc[g][q][b] = ffma2(wa, make_float2(h4[b].x, h4[b].y),     \
                                         acc[g][q][b]);                         \
                    acc[g][q][b] = ffma2(wb, make_float2(h4[b].z, h4[b].w),     \
                                         acc[g][q][b]);                         \
                }                                                               \
            }                                                                   \
    }

extern "C" __global__ void __launch_bounds__(NTH, 1) __cluster_dims__(GH, 1, 1)
momgru_kernel(const float* __restrict__ x,
              const float* __restrict__ W_ih,
              const float* __restrict__ W_hh,
              const float* __restrict__ b_ih,
              const float* __restrict__ b_hh,
              const float* __restrict__ Wb_x,
              const float* __restrict__ Wb_h,
              const float* __restrict__ b_beta,
              const float* __restrict__ s_ptr,
              const float* __restrict__ W_head,
              const float* __restrict__ b_head,
              float* __restrict__ out)
{
    extern __shared__ float sm[];
    float*  ws     = sm + OFF_W;
    float*  hbuf   = sm + OFF_H;        // [2][BB][RSH], k-permuted, DSMEM target
    float*  wbhs   = sm + OFF_WBH;      // k-permuted
    float*  whds   = sm + OFF_WHD;
    float*  beta_s = sm + OFF_BS;
    float2* xs     = (float2*)(sm + OFF_XS);

    const int tid = threadIdx.x;
    const int j   = blockIdx.x & (GH - 1);    // hidden block / cluster rank
    const int i   = blockIdx.x >> 2;          // batch block
    const int b0  = i * BB;
    const int u0  = j * UPC;

    const int up = tid >> 3;        // 0..31  u-pair index
    const int ks = tid & 7;         // 0..7   K-split lane
    const int uo = up * 2 + (ks >> 2);   // owned local u (0..63)
    const int bo = ks & 3;               // owned local batch (0..3)

    // ---- one-time preload (k-permuted: kl = (k - u0) mod 256) ---------------
    for (int e = tid; e < NROWS * HID; e += NTH) {
        int row = e >> 8;
        int k   = e & (HID - 1);
        int g   = row >> 6;
        int uu  = row & 63;
        int kl  = (k - u0) & (HID - 1);
        ws[row * RSW + kl] = W_hh[(g * HID + u0 + uu) * HID + k];
    }
    for (int e = tid; e < HID; e += NTH) {
        wbhs[(e - u0) & (HID - 1)] = Wb_h[e];
        whds[e] = W_head[e];
    }
    // zero both h buffers: h0 = 0 for step-0 reads everywhere
    for (int e = tid; e < 2 * HBUF; e += NTH) hbuf[e] = 0.0f;

    const float wbx0  = __ldg(Wb_x);
    const float wbx1  = __ldg(Wb_x + 1);
    const float bbeta = __ldg(b_beta);
    const float sv    = __ldg(s_ptr);
    const float bhead = __ldg(b_head);

    float2 wihg[3];
    float  bihg[3], bhhg[3];
    #pragma unroll
    for (int g = 0; g < 3; ++g) {
        int gr  = g * HID + u0 + uo;
        wihg[g] = make_float2(__ldg(W_ih + gr * 2), __ldg(W_ih + gr * 2 + 1));
        bihg[g] = __ldg(b_ih + gr);
        bhhg[g] = __ldg(b_hh + gr);
    }

    // DSMEM push addresses: this thread's (uo,bo) into each peer's buffer,
    // at the PEER's k-permuted position kl_p = (u0 + uo - 64p) mod 256.
    const unsigned hbase = smem_u32(hbuf);
    unsigned hpush[GH - 1];
    {
        int idx = 0;
        for (int p = 0; p < GH; ++p) {
            if (p == j) continue;
            int klp = ((u0 + uo) - UPC * p) & (HID - 1);
            hpush[idx++] = mapa_rank(hbase, (unsigned)p)
                         + (unsigned)(bo * RSH + klp) * 4u;
        }
    }

    __syncthreads();    // smem zeros + weights visible CTA-wide

    // weight row pointers (k-permuted base + ks lane offset)
    const float* wp[3][2];
    #pragma unroll
    for (int g = 0; g < 3; ++g)
        #pragma unroll
        for (int q = 0; q < 2; ++q)
            wp[g][q] = ws + (g * UPC + up * 2 + q) * RSW + ks * 4;

    // register-resident weights for own chunks 0-1 (static after permutation)
    float4 wreg[3][2][2];
    #pragma unroll
    for (int g = 0; g < 3; ++g)
        #pragma unroll
        for (int q = 0; q < 2; ++q)
            #pragma unroll
            for (int kk = 0; kk < 2; ++kk)
                wreg[g][q][kk] = *(const float4*)(wp[g][q] + kk * 32);

    CLUSTER_ARRIVE();   // release: peers may start reading (zeros) after wait

    // per-thread momentum state for (uo, bo)
    float v0 = 0.f, v1 = 0.f, v2 = 0.f;

    const int bb = tid >> 4;        // beta batch (tid<64): 0..3
    const int kc = tid & 15;        // beta K-chunk lane

    for (int t = 0; t < SEQ; ++t) {
        float* hcur = hbuf + (t & 1) * HBUF;
        float* hnxt = hbuf + ((t + 1) & 1) * HBUF;
        const unsigned boff = (unsigned)(((t + 1) & 1) * HBUF) * 4u;

        // x prefetch BEFORE the wait (independent of peers' h)
        float2 xv = make_float2(0.f, 0.f);
        if (tid < 64 && kc == 0)
            xv = __ldg((const float2*)x + (b0 + bb) * SEQ + t);

        float2 acc[3][2][4];
        #pragma unroll
        for (int g = 0; g < 3; ++g)
            #pragma unroll
            for (int q = 0; q < 2; ++q)
                #pragma unroll
                for (int b = 0; b < 4; ++b) acc[g][q][b] = make_float2(0.f, 0.f);

        // ---- chunks 0-1 (own k, local data, REGISTER weights) ---------------
        GEMM_CHUNK_REG(0);
        GEMM_CHUNK_REG(1);

        CLUSTER_WAIT();   // acquire: peers' pushes into hcur visible

        // ---- beta: h . Wb_h (warps 0-1; permuted order, same dot) -----------
        if (tid < 64) {
            const float* hrow = hcur + bb * RSH + kc * 4;
            const float* wrow = wbhs + kc * 4;
            float2 a2 = make_float2(0.f, 0.f);
            #pragma unroll
            for (int kk = 0; kk < 4; ++kk) {
                float4 h4 = *(const float4*)(hrow + kk * 64);
                float4 w4 = *(const float4*)(wrow + kk * 64);
                a2 = ffma2(make_float2(w4.x, w4.y), make_float2(h4.x, h4.y), a2);
                a2 = ffma2(make_float2(w4.z, w4.w), make_float2(h4.z, h4.w), a2);
            }
            float a = a2.x + a2.y;
            a += __shfl_xor_sync(0xffffffffu, a, 1);
            a += __shfl_xor_sync(0xffffffffu, a, 2);
            a += __shfl_xor_sync(0xffffffffu, a, 4);
            a += __shfl_xor_sync(0xffffffffu, a, 8);
            if (kc == 0) {
                float bval = sigf(xv.x * wbx0 + xv.y * wbx1 + a + bbeta);
                beta_s[bb] = bval;
                xs[bb]     = xv;
                if (j == 0) out[BATCH + (b0 + bb) * SEQ + t] = bval;
            }
        }

        // ---- main GEMM: local chunks 2..7 (peer data, smem weights) ---------
        #pragma unroll
        for (int kk = 2; kk < 8; ++kk) {
            GEMM_CHUNK(kk * 32);
        }

        // ---- reduce-scatter over ks lanes: thread keeps its own (uo,bo) -----
        float gh[3];
        #pragma unroll
        for (int g = 0; g < 3; ++g) {
            float v[8];
            #pragma unroll
            for (int q = 0; q < 2; ++q)
                #pragma unroll
                for (int b = 0; b < 4; ++b)
                    v[q * 4 + b] = acc[g][q][b].x + acc[g][q][b].y;
            gh[g] = reduce_scatter8(v, ks) + bhhg[g];
        }

        __syncthreads();   // beta_s / xs published; hcur reads of step t done

        // ---- v update + gates: thread owns (uo, bo) -------------------------
        {
            const float  be    = beta_s[bo];
            const float2 xv2   = xs[bo];
            const float  hprev = hcur[bo * RSH + uo];   // own u at kl=uo

            float pr = xv2.x * wihg[0].x + xv2.y * wihg[0].y + bihg[0];
            float pz = xv2.x * wihg[1].x + xv2.y * wihg[1].y + bihg[1];
            float pn = xv2.x * wihg[2].x + xv2.y * wihg[2].y + bihg[2];
            v0 = be * v0 + sv * pr;
            v1 = be * v1 + sv * pz;
            v2 = be * v2 + sv * pn;

            float r  = sigf(v0 + gh[0]);
            float z  = sigf(v1 + gh[1]);
            float n  = tanh_hw(v2 + r * gh[2]);
            float hn = (1.0f - z) * n + z * hprev;

            // publish h_{t+1}(u0+uo, bo): 3 DSMEM pushes + 1 local store
            st_cluster_f32(hpush[0] + boff, hn);
            st_cluster_f32(hpush[1] + boff, hn);
            st_cluster_f32(hpush[2] + boff, hn);
            hnxt[bo * RSH + uo] = hn;
        }

        CLUSTER_ARRIVE();  // release: pushes ordered before peers' next wait
        __syncthreads();   // own-region hnxt visible before next chunks 0-1
    }

    CLUSTER_WAIT();        // final pushes visible; h_T = buffer 0 in smem

    // ---- head: out[b] = h_T . W_head + b_head (rank-0 CTA; u0=0 -> natural) -
    if (j == 0 && tid < 64) {
        int b = tid >> 4;
        const float* hT = hbuf + b * RSH;          // buffer 0
        float2 a2 = make_float2(0.f, 0.f);
        #pragma unroll
        for (int kk = 0; kk < 4; ++kk) {
            float4 h4 = *(const float4*)(hT + kc * 4 + kk * 64);
            float4 w4 = *(const float4*)(whds + kc * 4 + kk * 64);
            a2 = ffma2(make_float2(w4.x, w4.y), make_float2(h4.x, h4.y), a2);
            a2 = ffma2(make_float2(w4.z, w4.w), make_float2(h4.z, h4.w), a2);
        }
        float a = a2.x + a2.y;
        a += __shfl_xor_sync(0xffffffffu, a, 1);
        a += __shfl_xor_sync(0xffffffffu, a, 2);
        a += __shfl_xor_sync(0xffffffffu, a, 4);
        a += __shfl_xor_sync(0xffffffffu, a, 8);
        if (kc == 0) out[b0 + b] = a + bhead;
    }

    CLUSTER_ARRIVE();      // no CTA exits while peers may still push into it
    CLUSTER_WAIT();
}

extern "C" void kernel_launch(void* const* d_in, const int* in_sizes, int n_in,
                              void* d_out, int out_size) {
    const float* x      = (const float*)d_in[0];
    const float* W_ih   = (const float*)d_in[1];
    const float* W_hh   = (const float*)d_in[2];
    const float* b_ih   = (const float*)d_in[3];
    const float* b_hh   = (const float*)d_in[4];
    const float* Wb_x   = (const float*)d_in[5];
    const float* Wb_h   = (const float*)d_in[6];
    const float* b_beta = (const float*)d_in[7];
    const float* s      = (const float*)d_in[8];
    const float* W_head = (const float*)d_in[9];
    const float* b_head = (const float*)d_in[10];

    cudaFuncSetAttribute(momgru_kernel,
                         cudaFuncAttributeMaxDynamicSharedMemorySize,
                         SMEM_BYTES);

    momgru_kernel<<<NCTA, NTH, SMEM_BYTES>>>(
        x, W_ih, W_hh, b_ih, b_hh, Wb_x, Wb_h, b_beta, s, W_head, b_head,
        (float*)d_out);
}

// round 13
// speedup vs baseline: 1.3935x; 1.1114x over previous
#include <cuda_runtime.h>

// ---------------------------------------------------------------------------
// MomGRU persistent recurrence, round 13 = R12 with register-resident weights
// extended to 4 k-chunks (0-3). Chunks 4-7 read weights from smem.
// Grid 128 CTAs = 32 batch-blocks x 4 hidden-blocks; cluster(4); 256 threads.
// K-permuted smem; h lives ONLY in smem ping-pong buffers; each thread owns
// one (u,b) value and pushes it to the 3 peer CTAs via st.shared::cluster.
// Own chunks 0-1 (register weights, local h) run before the cluster wait.
// ---------------------------------------------------------------------------

namespace {
constexpr int BATCH = 128;
constexpr int SEQ   = 1024;
constexpr int HID   = 256;
constexpr int GB    = 32;              // batch blocks
constexpr int GH    = 4;               // hidden blocks (= cluster size)
constexpr int NCTA  = GB * GH;         // 128
constexpr int BB    = BATCH / GB;      // 4 batches per CTA
constexpr int UPC   = HID / GH;        // 64 hidden units per CTA
constexpr int NROWS = 3 * UPC;         // 192 W_hh rows per CTA
constexpr int NTH   = 256;
constexpr int RSW   = HID + 16;        // 272 weight row stride (floats)
constexpr int RSH   = HID + 4;         // 260 h row stride (floats)
constexpr int HBUF  = BB * RSH;        // 1040 floats per h buffer

// smem layout (floats)
constexpr int OFF_W   = 0;                       // NROWS * RSW
constexpr int OFF_H   = OFF_W + NROWS * RSW;     // 2 * HBUF (ping-pong)
constexpr int OFF_WBH = OFF_H + 2 * HBUF;        // HID (k-permuted)
constexpr int OFF_WHD = OFF_WBH + HID;           // HID
constexpr int OFF_BS  = OFF_WHD + HID;           // BB
constexpr int OFF_XS  = OFF_BS + BB;             // BB float2
constexpr int SMEM_FLOATS = OFF_XS + BB * 2;
constexpr int SMEM_BYTES  = SMEM_FLOATS * 4;     // ~219.4 KB
}

// ---- packed fp32x2 helpers -------------------------------------------------
__device__ __forceinline__ unsigned long long pk2(float2 v) {
    unsigned long long r;
    asm("mov.b64 %0, {%1,%2};" : "=l"(r) : "f"(v.x), "f"(v.y));
    return r;
}
__device__ __forceinline__ float2 upk2(unsigned long long v) {
    float2 r;
    asm("mov.b64 {%0,%1}, %2;" : "=f"(r.x), "=f"(r.y) : "l"(v));
    return r;
}
__device__ __forceinline__ float2 ffma2(float2 a, float2 b, float2 c) {
    unsigned long long d;
    asm("fma.rn.f32x2 %0, %1, %2, %3;"
        : "=l"(d) : "l"(pk2(a)), "l"(pk2(b)), "l"(pk2(c)));
    return upk2(d);
}

// ---- HW tanh activations ----------------------------------------------------
__device__ __forceinline__ float tanh_hw(float x) {
    float r;
    asm("tanh.approx.f32 %0, %1;" : "=f"(r) : "f"(x));
    return r;
}
__device__ __forceinline__ float sigf(float x) {
    return 0.5f + 0.5f * tanh_hw(0.5f * x);
}

// ---- DSMEM helpers -----------------------------------------------------------
__device__ __forceinline__ unsigned smem_u32(const void* p) {
    unsigned a;
    asm("{ .reg .u64 t; cvta.to.shared.u64 t, %1; cvt.u32.u64 %0, t; }"
        : "=r"(a) : "l"(p));
    return a;
}
__device__ __forceinline__ unsigned mapa_rank(unsigned local, unsigned rank) {
    unsigned r;
    asm("mapa.shared::cluster.u32 %0, %1, %2;" : "=r"(r) : "r"(local), "r"(rank));
    return r;
}
__device__ __forceinline__ void st_cluster_f32(unsigned addr, float v) {
    asm volatile("st.shared::cluster.f32 [%0], %1;" :: "r"(addr), "f"(v) : "memory");
}

// Reduce-scatter over 8 ks lanes (R7-proven).
__device__ __forceinline__ float reduce_scatter8(const float v[8], int ks) {
    float w[4];
    #pragma unroll
    for (int i = 0; i < 4; ++i) {
        float mine  = (ks & 4) ? v[i + 4] : v[i];
        float their = (ks & 4) ? v[i]     : v[i + 4];
        w[i] = mine + __shfl_xor_sync(0xffffffffu, their, 4);
    }
    float y[2];
    #pragma unroll
    for (int i = 0; i < 2; ++i) {
        float mine  = (ks & 2) ? w[i + 2] : w[i];
        float their = (ks & 2) ? w[i]     : w[i + 2];
        y[i] = mine + __shfl_xor_sync(0xffffffffu, their, 2);
    }
    float mine  = (ks & 1) ? y[1] : y[0];
    float their = (ks & 1) ? y[0] : y[1];
    return mine + __shfl_xor_sync(0xffffffffu, their, 1);
}

#define CLUSTER_ARRIVE() asm volatile("barrier.cluster.arrive.aligned;" ::: "memory")
#define CLUSTER_WAIT()   asm volatile("barrier.cluster.wait.aligned;"   ::: "memory")

// GEMM k-chunk with weights from SMEM (chunks 4..7).
#define GEMM_CHUNK(o_)                                                          \
    {                                                                           \
        const int o = (o_);                                                     \
        float4 h4[4];                                                           \
        _Pragma("unroll")                                                       \
        for (int b = 0; b < 4; ++b)                                             \
            h4[b] = *(const float4*)(hcur + b * RSH + ks * 4 + o);              \
        _Pragma("unroll")                                                       \
        for (int g = 0; g < 3; ++g)                                             \
            _Pragma("unroll")                                                   \
            for (int q = 0; q < 2; ++q) {                                       \
                float4 w4 = *(const float4*)(wp[g][q] + o);                     \
                float2 wa = make_float2(w4.x, w4.y);                            \
                float2 wb = make_float2(w4.z, w4.w);                            \
                _Pragma("unroll")                                               \
                for (int b = 0; b < 4; ++b) {                                   \
                    acc[g][q][b] = ffma2(wa, make_float2(h4[b].x, h4[b].y),     \
                                         acc[g][q][b]);                         \
                    acc[g][q][b] = ffma2(wb, make_float2(h4[b].z, h4[b].w),     \
                                         acc[g][q][b]);                         \
                }                                                               \
            }                                                                   \
    }

// GEMM k-chunk with weights from REGISTERS (chunks 0..3; kkidx = 0..3).
#define GEMM_CHUNK_REG(kkidx)                                                   \
    {                                                                           \
        const int o = (kkidx) * 32;                                             \
        float4 h4[4];                                                           \
        _Pragma("unroll")                                                       \
        for (int b = 0; b < 4; ++b)                                             \
            h4[b] = *(const float4*)(hcur + b * RSH + ks * 4 + o);              \
        _Pragma("unroll")                                                       \
        for (int g = 0; g < 3; ++g)                                             \
            _Pragma("unroll")                                                   \
            for (int q = 0; q < 2; ++q) {                                       \
                float4 w4 = wreg[g][q][kkidx];                                  \
                float2 wa = make_float2(w4.x, w4.y);                            \
                float2 wb = make_float2(w4.z, w4.w);                            \
                _Pragma("unroll")                                               \
                for (int b = 0; b < 4; ++b) {                                   \
                    acc[g][q][b] = ffma2(wa, make_float2(h4[b].x, h4[b].y),     \
                                         acc[g][q][b]);                         \
                    acc[g][q][b] = ffma2(wb, make_float2(h4[b].z, h4[b].w),     \
                                         acc[g][q][b]);                         \
                }                                                               \
            }                                                                   \
    }

extern "C" __global__ void __launch_bounds__(NTH, 1) __cluster_dims__(GH, 1, 1)
momgru_kernel(const float* __restrict__ x,
              const float* __restrict__ W_ih,
              const float* __restrict__ W_hh,
              const float* __restrict__ b_ih,
              const float* __restrict__ b_hh,
              const float* __restrict__ Wb_x,
              const float* __restrict__ Wb_h,
              const float* __restrict__ b_beta,
              const float* __restrict__ s_ptr,
              const float* __restrict__ W_head,
              const float* __restrict__ b_head,
              float* __restrict__ out)
{
    extern __shared__ float sm[];
    float*  ws     = sm + OFF_W;
    float*  hbuf   = sm + OFF_H;        // [2][BB][RSH], k-permuted, DSMEM target
    float*  wbhs   = sm + OFF_WBH;      // k-permuted
    float*  whds   = sm + OFF_WHD;
    float*  beta_s = sm + OFF_BS;
    float2* xs     = (float2*)(sm + OFF_XS);

    const int tid = threadIdx.x;
    const int j   = blockIdx.x & (GH - 1);    // hidden block / cluster rank
    const int i   = blockIdx.x >> 2;          // batch block
    const int b0  = i * BB;
    const int u0  = j * UPC;

    const int up = tid >> 3;        // 0..31  u-pair index
    const int ks = tid & 7;         // 0..7   K-split lane
    const int uo = up * 2 + (ks >> 2);   // owned local u (0..63)
    const int bo = ks & 3;               // owned local batch (0..3)

    // ---- one-time preload (k-permuted: kl = (k - u0) mod 256) ---------------
    for (int e = tid; e < NROWS * HID; e += NTH) {
        int row = e >> 8;
        int k   = e & (HID - 1);
        int g   = row >> 6;
        int uu  = row & 63;
        int kl  = (k - u0) & (HID - 1);
        ws[row * RSW + kl] = W_hh[(g * HID + u0 + uu) * HID + k];
    }
    for (int e = tid; e < HID; e += NTH) {
        wbhs[(e - u0) & (HID - 1)] = Wb_h[e];
        whds[e] = W_head[e];
    }
    // zero both h buffers: h0 = 0 for step-0 reads everywhere
    for (int e = tid; e < 2 * HBUF; e += NTH) hbuf[e] = 0.0f;

    const float wbx0  = __ldg(Wb_x);
    const float wbx1  = __ldg(Wb_x + 1);
    const float bbeta = __ldg(b_beta);
    const float sv    = __ldg(s_ptr);
    const float bhead = __ldg(b_head);

    float2 wihg[3];
    float  bihg[3], bhhg[3];
    #pragma unroll
    for (int g = 0; g < 3; ++g) {
        int gr  = g * HID + u0 + uo;
        wihg[g] = make_float2(__ldg(W_ih + gr * 2), __ldg(W_ih + gr * 2 + 1));
        bihg[g] = __ldg(b_ih + gr);
        bhhg[g] = __ldg(b_hh + gr);
    }

    // DSMEM push addresses: this thread's (uo,bo) into each peer's buffer,
    // at the PEER's k-permuted position kl_p = (u0 + uo - 64p) mod 256.
    const unsigned hbase = smem_u32(hbuf);
    unsigned hpush[GH - 1];
    {
        int idx = 0;
        for (int p = 0; p < GH; ++p) {
            if (p == j) continue;
            int klp = ((u0 + uo) - UPC * p) & (HID - 1);
            hpush[idx++] = mapa_rank(hbase, (unsigned)p)
                         + (unsigned)(bo * RSH + klp) * 4u;
        }
    }

    __syncthreads();    // smem zeros + weights visible CTA-wide

    // weight row pointers (k-permuted base + ks lane offset)
    const float* wp[3][2];
    #pragma unroll
    for (int g = 0; g < 3; ++g)
        #pragma unroll
        for (int q = 0; q < 2; ++q)
            wp[g][q] = ws + (g * UPC + up * 2 + q) * RSW + ks * 4;

    // register-resident weights for chunks 0-3 (static after permutation)
    float4 wreg[3][2][4];
    #pragma unroll
    for (int g = 0; g < 3; ++g)
        #pragma unroll
        for (int q = 0; q < 2; ++q)
            #pragma unroll
            for (int kk = 0; kk < 4; ++kk)
                wreg[g][q][kk] = *(const float4*)(wp[g][q] + kk * 32);

    CLUSTER_ARRIVE();   // release: peers may start reading (zeros) after wait

    // per-thread momentum state for (uo, bo)
    float v0 = 0.f, v1 = 0.f, v2 = 0.f;

    const int bb = tid >> 4;        // beta batch (tid<64): 0..3
    const int kc = tid & 15;        // beta K-chunk lane

    for (int t = 0; t < SEQ; ++t) {
        float* hcur = hbuf + (t & 1) * HBUF;
        float* hnxt = hbuf + ((t + 1) & 1) * HBUF;
        const unsigned boff = (unsigned)(((t + 1) & 1) * HBUF) * 4u;

        // x prefetch BEFORE the wait (independent of peers' h)
        float2 xv = make_float2(0.f, 0.f);
        if (tid < 64 && kc == 0)
            xv = __ldg((const float2*)x + (b0 + bb) * SEQ + t);

        float2 acc[3][2][4];
        #pragma unroll
        for (int g = 0; g < 3; ++g)
            #pragma unroll
            for (int q = 0; q < 2; ++q)
                #pragma unroll
                for (int b = 0; b < 4; ++b) acc[g][q][b] = make_float2(0.f, 0.f);

        // ---- chunks 0-1 (own k, local data, REGISTER weights) ---------------
        GEMM_CHUNK_REG(0);
        GEMM_CHUNK_REG(1);

        CLUSTER_WAIT();   // acquire: peers' pushes into hcur visible

        // ---- beta: h . Wb_h (warps 0-1; permuted order, same dot) -----------
        if (tid < 64) {
            const float* hrow = hcur + bb * RSH + kc * 4;
            const float* wrow = wbhs + kc * 4;
            float2 a2 = make_float2(0.f, 0.f);
            #pragma unroll
            for (int kk = 0; kk < 4; ++kk) {
                float4 h4 = *(const float4*)(hrow + kk * 64);
                float4 w4 = *(const float4*)(wrow + kk * 64);
                a2 = ffma2(make_float2(w4.x, w4.y), make_float2(h4.x, h4.y), a2);
                a2 = ffma2(make_float2(w4.z, w4.w), make_float2(h4.z, h4.w), a2);
            }
            float a = a2.x + a2.y;
            a += __shfl_xor_sync(0xffffffffu, a, 1);
            a += __shfl_xor_sync(0xffffffffu, a, 2);
            a += __shfl_xor_sync(0xffffffffu, a, 4);
            a += __shfl_xor_sync(0xffffffffu, a, 8);
            if (kc == 0) {
                float bval = sigf(xv.x * wbx0 + xv.y * wbx1 + a + bbeta);
                beta_s[bb] = bval;
                xs[bb]     = xv;
                if (j == 0) out[BATCH + (b0 + bb) * SEQ + t] = bval;
            }
        }

        // ---- chunks 2-3 (peer data, REGISTER weights) ------------------------
        GEMM_CHUNK_REG(2);
        GEMM_CHUNK_REG(3);

        // ---- chunks 4-7 (peer data, smem weights) ----------------------------
        #pragma unroll
        for (int kk = 4; kk < 8; ++kk) {
            GEMM_CHUNK(kk * 32);
        }

        // ---- reduce-scatter over ks lanes: thread keeps its own (uo,bo) -----
        float gh[3];
        #pragma unroll
        for (int g = 0; g < 3; ++g) {
            float v[8];
            #pragma unroll
            for (int q = 0; q < 2; ++q)
                #pragma unroll
                for (int b = 0; b < 4; ++b)
                    v[q * 4 + b] = acc[g][q][b].x + acc[g][q][b].y;
            gh[g] = reduce_scatter8(v, ks) + bhhg[g];
        }

        __syncthreads();   // beta_s / xs published; hcur reads of step t done

        // ---- v update + gates: thread owns (uo, bo) -------------------------
        {
            const float  be    = beta_s[bo];
            const float2 xv2   = xs[bo];
            const float  hprev = hcur[bo * RSH + uo];   // own u at kl=uo

            float pr = xv2.x * wihg[0].x + xv2.y * wihg[0].y + bihg[0];
            float pz = xv2.x * wihg[1].x + xv2.y * wihg[1].y + bihg[1];
            float pn = xv2.x * wihg[2].x + xv2.y * wihg[2].y + bihg[2];
            v0 = be * v0 + sv * pr;
            v1 = be * v1 + sv * pz;
            v2 = be * v2 + sv * pn;

            float r  = sigf(v0 + gh[0]);
            float z  = sigf(v1 + gh[1]);
            float n  = tanh_hw(v2 + r * gh[2]);
            float hn = (1.0f - z) * n + z * hprev;

            // publish h_{t+1}(u0+uo, bo): 3 DSMEM pushes + 1 local store
            st_cluster_f32(hpush[0] + boff, hn);
            st_cluster_f32(hpush[1] + boff, hn);
            st_cluster_f32(hpush[2] + boff, hn);
            hnxt[bo * RSH + uo] = hn;
        }

        CLUSTER_ARRIVE();  // release: pushes ordered before peers' next wait
        __syncthreads();   // own-region hnxt visible before next chunks 0-1
    }

    CLUSTER_WAIT();        // final pushes visible; h_T = buffer 0 in smem

    // ---- head: out[b] = h_T . W_head + b_head (rank-0 CTA; u0=0 -> natural) -
    if (j == 0 && tid < 64) {
        int b = tid >> 4;
        const float* hT = hbuf + b * RSH;          // buffer 0
        float2 a2 = make_float2(0.f, 0.f);
        #pragma unroll
        for (int kk = 0; kk < 4; ++kk) {
            float4 h4 = *(const float4*)(hT + kc * 4 + kk * 64);
            float4 w4 = *(const float4*)(whds + kc * 4 + kk * 64);
            a2 = ffma2(make_float2(w4.x, w4.y), make_float2(h4.x, h4.y), a2);
            a2 = ffma2(make_float2(w4.z, w4.w), make_float2(h4.z, h4.w), a2);
        }
        float a = a2.x + a2.y;
        a += __shfl_xor_sync(0xffffffffu, a, 1);
        a += __shfl_xor_sync(0xffffffffu, a, 2);
        a += __shfl_xor_sync(0xffffffffu, a, 4);
        a += __shfl_xor_sync(0xffffffffu, a, 8);
        if (kc == 0) out[b0 + b] = a + bhead;
    }

    CLUSTER_ARRIVE();      // no CTA exits while peers may still push into it
    CLUSTER_WAIT();
}

extern "C" void kernel_launch(void* const* d_in, const int* in_sizes, int n_in,
                              void* d_out, int out_size) {
    const float* x      = (const float*)d_in[0];
    const float* W_ih   = (const float*)d_in[1];
    const float* W_hh   = (const float*)d_in[2];
    const float* b_ih   = (const float*)d_in[3];
    const float* b_hh   = (const float*)d_in[4];
    const float* Wb_x   = (const float*)d_in[5];
    const float* Wb_h   = (const float*)d_in[6];
    const float* b_beta = (const float*)d_in[7];
    const float* s      = (const float*)d_in[8];
    const float* W_head = (const float*)d_in[9];
    const float* b_head = (const float*)d_in[10];

    cudaFuncSetAttribute(momgru_kernel,
                         cudaFuncAttributeMaxDynamicSharedMemorySize,
                         SMEM_BYTES);

    momgru_kernel<<<NCTA, NTH, SMEM_BYTES>>>(
        x, W_ih, W_hh, b_ih, b_hh, Wb_x, Wb_h, b_beta, s, W_head, b_head,
        (float*)d_out);
}

// round 14
// speedup vs baseline: 1.7785x; 1.2763x over previous
#include <cuda_runtime.h>

// ---------------------------------------------------------------------------
// MomGRU persistent recurrence, round 14 = R13 with the cluster barrier
// replaced by st.async pushes + transaction mbarriers.
// Grid 128 CTAs = 32 batch-blocks x 4 hidden-blocks; cluster(4); 256 threads.
// K-permuted smem; register weights for k-chunks 0-3; h lives only in smem
// ping-pong buffers. Each thread pushes its (u,b) value to the 3 peers via
// st.async.shared::cluster.mbarrier::complete_tx::bytes targeting the peer's
// ping-pong mbarrier; consumers try_wait (parity, acquire) -- no
// barrier.cluster, no fence in the recurrence.
// ---------------------------------------------------------------------------

namespace {
constexpr int BATCH = 128;
constexpr int SEQ   = 1024;
constexpr int HID   = 256;
constexpr int GB    = 32;              // batch blocks
constexpr int GH    = 4;               // hidden blocks (= cluster size)
constexpr int NCTA  = GB * GH;         // 128
constexpr int BB    = BATCH / GB;      // 4 batches per CTA
constexpr int UPC   = HID / GH;        // 64 hidden units per CTA
constexpr int NROWS = 3 * UPC;         // 192 W_hh rows per CTA
constexpr int NTH   = 256;
constexpr int RSW   = HID + 16;        // 272 weight row stride (floats)
constexpr int RSH   = HID + 4;         // 260 h row stride (floats)
constexpr int HBUF  = BB * RSH;        // 1040 floats per h buffer
constexpr unsigned TX_BYTES = (GH - 1) * NTH * 4;   // 3072 incoming bytes/step

// smem layout (floats)
constexpr int OFF_MBAR = 0;                      // 2 mbarriers (16 B)
constexpr int OFF_W   = 4;                       // NROWS * RSW
constexpr int OFF_H   = OFF_W + NROWS * RSW;     // 2 * HBUF (ping-pong)
constexpr int OFF_WBH = OFF_H + 2 * HBUF;        // HID (k-permuted)
constexpr int OFF_WHD = OFF_WBH + HID;           // HID
constexpr int OFF_BS  = OFF_WHD + HID;           // BB
constexpr int OFF_XS  = OFF_BS + BB;             // BB float2
constexpr int SMEM_FLOATS = OFF_XS + BB * 2;
constexpr int SMEM_BYTES  = SMEM_FLOATS * 4;     // ~219.4 KB
}

// ---- packed fp32x2 helpers -------------------------------------------------
__device__ __forceinline__ unsigned long long pk2(float2 v) {
    unsigned long long r;
    asm("mov.b64 %0, {%1,%2};" : "=l"(r) : "f"(v.x), "f"(v.y));
    return r;
}
__device__ __forceinline__ float2 upk2(unsigned long long v) {
    float2 r;
    asm("mov.b64 {%0,%1}, %2;" : "=f"(r.x), "=f"(r.y) : "l"(v));
    return r;
}
__device__ __forceinline__ float2 ffma2(float2 a, float2 b, float2 c) {
    unsigned long long d;
    asm("fma.rn.f32x2 %0, %1, %2, %3;"
        : "=l"(d) : "l"(pk2(a)), "l"(pk2(b)), "l"(pk2(c)));
    return upk2(d);
}

// ---- HW tanh activations ----------------------------------------------------
__device__ __forceinline__ float tanh_hw(float x) {
    float r;
    asm("tanh.approx.f32 %0, %1;" : "=f"(r) : "f"(x));
    return r;
}
__device__ __forceinline__ float sigf(float x) {
    return 0.5f + 0.5f * tanh_hw(0.5f * x);
}

// ---- DSMEM / mbarrier helpers -----------------------------------------------
__device__ __forceinline__ unsigned smem_u32(const void* p) {
    unsigned a;
    asm("{ .reg .u64 t; cvta.to.shared.u64 t, %1; cvt.u32.u64 %0, t; }"
        : "=r"(a) : "l"(p));
    return a;
}
__device__ __forceinline__ unsigned mapa_rank(unsigned local, unsigned rank) {
    unsigned r;
    asm("mapa.shared::cluster.u32 %0, %1, %2;" : "=r"(r) : "r"(local), "r"(rank));
    return r;
}
__device__ __forceinline__ void st_async_f32(unsigned raddr, float v, unsigned rmbar) {
    asm volatile(
        "st.async.shared::cluster.mbarrier::complete_tx::bytes.f32 [%0], %1, [%2];"
        :: "r"(raddr), "f"(v), "r"(rmbar) : "memory");
}
__device__ __forceinline__ void mbar_init(unsigned mbar, unsigned cnt) {
    asm volatile("mbarrier.init.shared.b64 [%0], %1;" :: "r"(mbar), "r"(cnt) : "memory");
}
__device__ __forceinline__ void mbar_expect_tx(unsigned mbar, unsigned bytes) {
    asm volatile("mbarrier.arrive.expect_tx.shared.b64 _, [%0], %1;"
                 :: "r"(mbar), "r"(bytes) : "memory");
}
__device__ __forceinline__ void mbar_wait(unsigned mbar, unsigned parity) {
    unsigned done;
    asm volatile(
        "{\n\t.reg .pred p;\n\t"
        "mbarrier.try_wait.parity.acquire.cluster.shared::cta.b64 p, [%1], %2;\n\t"
        "selp.b32 %0, 1, 0, p;\n\t}"
        : "=r"(done) : "r"(mbar), "r"(parity) : "memory");
    if (!done) {
        asm volatile(
            "{\n\t.reg .pred P1;\n\t"
            "WL_%=:\n\t"
            "mbarrier.try_wait.parity.acquire.cluster.shared::cta.b64 P1, [%0], %1, 0x989680;\n\t"
            "@P1 bra.uni WD_%=;\n\t"
            "bra.uni WL_%=;\n\t"
            "WD_%=:\n\t}"
            :: "r"(mbar), "r"(parity) : "memory");
    }
}
#define CLUSTER_SYNC_() do {                                          \
    asm volatile("barrier.cluster.arrive.aligned;" ::: "memory");     \
    asm volatile("barrier.cluster.wait.aligned;"   ::: "memory");     \
} while (0)

// GEMM k-chunk with weights from SMEM (chunks 4..7).
#define GEMM_CHUNK(o_)                                                          \
    {                                                                           \
        const int o = (o_);                                                     \
        float4 h4[4];                                                           \
        _Pragma("unroll")                                                       \
        for (int b = 0; b < 4; ++b)                                             \
            h4[b] = *(const float4*)(hcur + b * RSH + ks * 4 + o);              \
        _Pragma("unroll")                                                       \
        for (int g = 0; g < 3; ++g)                                             \
            _Pragma("unroll")                                                   \
            for (int q = 0; q < 2; ++q) {                                       \
                float4 w4 = *(const float4*)(wp[g][q] + o);                     \
                float2 wa = make_float2(w4.x, w4.y);                            \
                float2 wb = make_float2(w4.z, w4.w);                            \
                _Pragma("unroll")                                               \
                for (int b = 0; b < 4; ++b) {                                   \
                    acc[g][q][b] = ffma2(wa, make_float2(h4[b].x, h4[b].y),     \
                                         acc[g][q][b]);                         \
                    acc[g][q][b] = ffma2(wb, make_float2(h4[b].z, h4[b].w),     \
                                         acc[g][q][b]);                         \
                }                                                               \
            }                                                                   \
    }

// GEMM k-chunk with weights from REGISTERS (chunks 0..3; kkidx = 0..3).
#define GEMM_CHUNK_REG(kkidx)                                                   \
    {                                                                           \
        const int o = (kkidx) * 32;                                             \
        float4 h4[4];                                                           \
        _Pragma("unroll")                                                       \
        for (int b = 0; b < 4; ++b)                                             \
            h4[b] = *(const float4*)(hcur + b * RSH + ks * 4 + o);              \
        _Pragma("unroll")                                                       \
        for (int g = 0; g < 3; ++g)                                             \
            _Pragma("unroll")                                                   \
            for (int q = 0; q < 2; ++q) {                                       \
                float4 w4 = wreg[g][q][kkidx];                                  \
                float2 wa = make_float2(w4.x, w4.y);                            \
                float2 wb = make_float2(w4.z, w4.w);                            \
                _Pragma("unroll")                                               \
                for (int b = 0; b < 4; ++b) {                                   \
                    acc[g][q][b] = ffma2(wa, make_float2(h4[b].x, h4[b].y),     \
                                         acc[g][q][b]);                         \
                    acc[g][q][b] = ffma2(wb, make_float2(h4[b].z, h4[b].w),     \
                                         acc[g][q][b]);                         \
                }                                                               \
            }                                                                   \
    }

extern "C" __global__ void __launch_bounds__(NTH, 1) __cluster_dims__(GH, 1, 1)
momgru_kernel(const float* __restrict__ x,
              const float* __restrict__ W_ih,
              const float* __restrict__ W_hh,
              const float* __restrict__ b_ih,
              const float* __restrict__ b_hh,
              const float* __restrict__ Wb_x,
              const float* __restrict__ Wb_h,
              const float* __restrict__ b_beta,
              const float* __restrict__ s_ptr,
              const float* __restrict__ W_head,
              const float* __restrict__ b_head,
              float* __restrict__ out)
{
    extern __shared__ float sm[];
    float*  ws     = sm + OFF_W;
    float*  hbuf   = sm + OFF_H;        // [2][BB][RSH], k-permuted, st.async tgt
    float*  wbhs   = sm + OFF_WBH;      // k-permuted
    float*  whds   = sm + OFF_WHD;
    float*  beta_s = sm + OFF_BS;
    float2* xs     = (float2*)(sm + OFF_XS);

    const unsigned sbase = smem_u32(sm);
    const unsigned mbar0 = sbase + OFF_MBAR * 4;   // mbar[s] = mbar0 + 8*s

    const int tid = threadIdx.x;
    const int j   = blockIdx.x & (GH - 1);    // hidden block / cluster rank
    const int i   = blockIdx.x >> 2;          // batch block
    const int b0  = i * BB;
    const int u0  = j * UPC;

    const int up = tid >> 3;        // 0..31  u-pair index
    const int ks = tid & 7;         // 0..7   K-split lane
    const int uo = up * 2 + (ks >> 2);   // owned local u (0..63)
    const int bo = ks & 3;               // owned local batch (0..3)

    // ---- one-time preload (k-permuted: kl = (k - u0) mod 256) ---------------
    for (int e = tid; e < NROWS * HID; e += NTH) {
        int row = e >> 8;
        int k   = e & (HID - 1);
        int g   = row >> 6;
        int uu  = row & 63;
        int kl  = (k - u0) & (HID - 1);
        ws[row * RSW + kl] = W_hh[(g * HID + u0 + uu) * HID + k];
    }
    for (int e = tid; e < HID; e += NTH) {
        wbhs[(e - u0) & (HID - 1)] = Wb_h[e];
        whds[e] = W_head[e];
    }
    // zero both h buffers: h0 = 0 for step-0 reads everywhere
    for (int e = tid; e < 2 * HBUF; e += NTH) hbuf[e] = 0.0f;

    const float wbx0  = __ldg(Wb_x);
    const float wbx1  = __ldg(Wb_x + 1);
    const float bbeta = __ldg(b_beta);
    const float sv    = __ldg(s_ptr);
    const float bhead = __ldg(b_head);

    float2 wihg[3];
    float  bihg[3], bhhg[3];
    #pragma unroll
    for (int g = 0; g < 3; ++g) {
        int gr  = g * HID + u0 + uo;
        wihg[g] = make_float2(__ldg(W_ih + gr * 2), __ldg(W_ih + gr * 2 + 1));
        bihg[g] = __ldg(b_ih + gr);
        bhhg[g] = __ldg(b_hh + gr);
    }

    // Remote addresses: this thread's (uo,bo) slot + peer mbarriers.
    const unsigned hbase = smem_u32(hbuf);
    unsigned hpush[GH - 1];
    unsigned pmbar[GH - 1];     // peer mbar0 (add 8*buf at use)
    {
        int idx = 0;
        for (int p = 0; p < GH; ++p) {
            if (p == j) continue;
            int klp = ((u0 + uo) - UPC * p) & (HID - 1);
            hpush[idx] = mapa_rank(hbase, (unsigned)p)
                       + (unsigned)(bo * RSH + klp) * 4u;
            pmbar[idx] = mapa_rank(mbar0, (unsigned)p);
            ++idx;
        }
    }

    if (tid == 0) { mbar_init(mbar0, 1u); mbar_init(mbar0 + 8, 1u); }
    __syncthreads();    // smem zeros + weights + mbarriers visible CTA-wide
    CLUSTER_SYNC_();    // once: peers' mbarrier init + zeros before any st.async

    // weight row pointers (k-permuted base + ks lane offset)
    const float* wp[3][2];
    #pragma unroll
    for (int g = 0; g < 3; ++g)
        #pragma unroll
        for (int q = 0; q < 2; ++q)
            wp[g][q] = ws + (g * UPC + up * 2 + q) * RSW + ks * 4;

    // register-resident weights for chunks 0-3
    float4 wreg[3][2][4];
    #pragma unroll
    for (int g = 0; g < 3; ++g)
        #pragma unroll
        for (int q = 0; q < 2; ++q)
            #pragma unroll
            for (int kk = 0; kk < 4; ++kk)
                wreg[g][q][kk] = *(const float4*)(wp[g][q] + kk * 32);

    // per-thread momentum state for (uo, bo)
    float v0 = 0.f, v1 = 0.f, v2 = 0.f;

    const int bb = tid >> 4;        // beta batch (tid<64): 0..3
    const int kc = tid & 15;        // beta K-chunk lane

    unsigned ph0 = 0, ph1 = 0;      // parity per mbarrier

    for (int t = 0; t < SEQ; ++t) {
        float* hcur = hbuf + (t & 1) * HBUF;
        float* hnxt = hbuf + ((t + 1) & 1) * HBUF;
        const int nb = (t + 1) & 1;                       // next buffer index
        const unsigned boff = (unsigned)(nb * HBUF) * 4u;

        // arm next phase's incoming-bytes expectation (single arrival, count=1)
        if (tid == 0) mbar_expect_tx(mbar0 + 8u * nb, TX_BYTES);

        // x prefetch BEFORE the wait (independent of peers' h)
        float2 xv = make_float2(0.f, 0.f);
        if (tid < 64 && kc == 0)
            xv = __ldg((const float2*)x + (b0 + bb) * SEQ + t);

        float2 acc[3][2][4];
        #pragma unroll
        for (int g = 0; g < 3; ++g)
            #pragma unroll
            for (int q = 0; q < 2; ++q)
                #pragma unroll
                for (int b = 0; b < 4; ++b) acc[g][q][b] = make_float2(0.f, 0.f);

        // ---- chunks 0-1 (own k, local data, REGISTER weights) ---------------
        GEMM_CHUNK_REG(0);
        GEMM_CHUNK_REG(1);

        // ---- wait: peers' st.async pushes for step t complete ----------------
        if (t > 0) {
            if (t & 1) { mbar_wait(mbar0 + 8, ph1); ph1 ^= 1; }
            else       { mbar_wait(mbar0,     ph0); ph0 ^= 1; }
        }

        // ---- beta: h . Wb_h (warps 0-1; permuted order, same dot) -----------
        if (tid < 64) {
            const float* hrow = hcur + bb * RSH + kc * 4;
            const float* wrow = wbhs + kc * 4;
            float2 a2 = make_float2(0.f, 0.f);
            #pragma unroll
            for (int kk = 0; kk < 4; ++kk) {
                float4 h4 = *(const float4*)(hrow + kk * 64);
                float4 w4 = *(const float4*)(wrow + kk * 64);
                a2 = ffma2(make_float2(w4.x, w4.y), make_float2(h4.x, h4.y), a2);
                a2 = ffma2(make_float2(w4.z, w4.w), make_float2(h4.z, h4.w), a2);
            }
            float a = a2.x + a2.y;
            a += __shfl_xor_sync(0xffffffffu, a, 1);
            a += __shfl_xor_sync(0xffffffffu, a, 2);
            a += __shfl_xor_sync(0xffffffffu, a, 4);
            a += __shfl_xor_sync(0xffffffffu, a, 8);
            if (kc == 0) {
                float bval = sigf(xv.x * wbx0 + xv.y * wbx1 + a + bbeta);
                beta_s[bb] = bval;
                xs[bb]     = xv;
                if (j == 0) out[BATCH + (b0 + bb) * SEQ + t] = bval;
            }
        }

        // ---- chunks 2-3 (peer data, REGISTER weights) ------------------------
        GEMM_CHUNK_REG(2);
        GEMM_CHUNK_REG(3);

        // ---- chunks 4-7 (peer data, smem weights) ----------------------------
        #pragma unroll
        for (int kk = 4; kk < 8; ++kk) {
            GEMM_CHUNK(kk * 32);
        }

        // ---- reduce-scatter over ks lanes (R7-proven butterfly) --------------
        float gh[3];
        #pragma unroll
        for (int g = 0; g < 3; ++g) {
            float v[8];
            #pragma unroll
            for (int q = 0; q < 2; ++q)
                #pragma unroll
                for (int b = 0; b < 4; ++b)
                    v[q * 4 + b] = acc[g][q][b].x + acc[g][q][b].y;
            // inline reduce_scatter8
            float w[4];
            #pragma unroll
            for (int ii = 0; ii < 4; ++ii) {
                float mine  = (ks & 4) ? v[ii + 4] : v[ii];
                float their = (ks & 4) ? v[ii]     : v[ii + 4];
                w[ii] = mine + __shfl_xor_sync(0xffffffffu, their, 4);
            }
            float y[2];
            #pragma unroll
            for (int ii = 0; ii < 2; ++ii) {
                float mine  = (ks & 2) ? w[ii + 2] : w[ii];
                float their = (ks & 2) ? w[ii]     : w[ii + 2];
                y[ii] = mine + __shfl_xor_sync(0xffffffffu, their, 2);
            }
            float mine  = (ks & 1) ? y[1] : y[0];
            float their = (ks & 1) ? y[0] : y[1];
            gh[g] = mine + __shfl_xor_sync(0xffffffffu, their, 1) + bhhg[g];
        }

        __syncthreads();   // beta_s / xs published; hcur reads of step t done

        // ---- v update + gates: thread owns (uo, bo) -------------------------
        {
            const float  be    = beta_s[bo];
            const float2 xv2   = xs[bo];
            const float  hprev = hcur[bo * RSH + uo];   // own u at kl=uo

            float pr = xv2.x * wihg[0].x + xv2.y * wihg[0].y + bihg[0];
            float pz = xv2.x * wihg[1].x + xv2.y * wihg[1].y + bihg[1];
            float pn = xv2.x * wihg[2].x + xv2.y * wihg[2].y + bihg[2];
            v0 = be * v0 + sv * pr;
            v1 = be * v1 + sv * pz;
            v2 = be * v2 + sv * pn;

            float r  = sigf(v0 + gh[0]);
            float z  = sigf(v1 + gh[1]);
            float n  = tanh_hw(v2 + r * gh[2]);
            float hn = (1.0f - z) * n + z * hprev;

            // publish h_{t+1}(u0+uo, bo): 3 self-tracking remote pushes + local
            const unsigned mb = 8u * (unsigned)nb;
            st_async_f32(hpush[0] + boff, hn, pmbar[0] + mb);
            st_async_f32(hpush[1] + boff, hn, pmbar[1] + mb);
            st_async_f32(hpush[2] + boff, hn, pmbar[2] + mb);
            hnxt[bo * RSH + uo] = hn;
        }

        __syncthreads();   // own-region hnxt visible before next chunks 0-1
    }

    // last pushes target mbar[SEQ&1] = mbar0; wait for final h_T
    mbar_wait(mbar0, ph0);

    // ---- head: out[b] = h_T . W_head + b_head (rank-0 CTA; u0=0 -> natural) -
    if (j == 0 && tid < 64) {
        int b = tid >> 4;
        const float* hT = hbuf + b * RSH;          // buffer 0
        float2 a2 = make_float2(0.f, 0.f);
        #pragma unroll
        for (int kk = 0; kk < 4; ++kk) {
            float4 h4 = *(const float4*)(hT + kc * 4 + kk * 64);
            float4 w4 = *(const float4*)(whds + kc * 4 + kk * 64);
            a2 = ffma2(make_float2(w4.x, w4.y), make_float2(h4.x, h4.y), a2);
            a2 = ffma2(make_float2(w4.z, w4.w), make_float2(h4.z, h4.w), a2);
        }
        float a = a2.x + a2.y;
        a += __shfl_xor_sync(0xffffffffu, a, 1);
        a += __shfl_xor_sync(0xffffffffu, a, 2);
        a += __shfl_xor_sync(0xffffffffu, a, 4);
        a += __shfl_xor_sync(0xffffffffu, a, 8);
        if (kc == 0) out[b0 + b] = a + bhead;
    }

    CLUSTER_SYNC_();    // no CTA exits while peers may still push into it
}

extern "C" void kernel_launch(void* const* d_in, const int* in_sizes, int n_in,
                              void* d_out, int out_size) {
    const float* x      = (const float*)d_in[0];
    const float* W_ih   = (const float*)d_in[1];
    const float* W_hh   = (const float*)d_in[2];
    const float* b_ih   = (const float*)d_in[3];
    const float* b_hh   = (const float*)d_in[4];
    const float* Wb_x   = (const float*)d_in[5];
    const float* Wb_h   = (const float*)d_in[6];
    const float* b_beta = (const float*)d_in[7];
    const float* s      = (const float*)d_in[8];
    const float* W_head = (const float*)d_in[9];
    const float* b_head = (const float*)d_in[10];

    cudaFuncSetAttribute(momgru_kernel,
                         cudaFuncAttributeMaxDynamicSharedMemorySize,
                         SMEM_BYTES);

    momgru_kernel<<<NCTA, NTH, SMEM_BYTES>>>(
        x, W_ih, W_hh, b_ih, b_hh, Wb_x, Wb_h, b_beta, s, W_head, b_head,
        (float*)d_out);
}